// round 10
// baseline (speedup 1.0000x reference)
#include <cuda_runtime.h>
#include <cuda_fp16.h>
#include <mma.h>

using namespace nvcuda;

// Problem constants (fixed by the dataset)
#define NN 50000
#define NPAD 50048              // 782 * 64 (wmma M-tile padding)
#define EE 800000
#define EAX (EE + NN)           // edges + self loops

// ---------------- scratch (device globals; no allocations allowed) ----------
__device__ __half g_hh[(size_t)NPAD * 256];  // fp16 features (wmma writes, aggregate reads)
__device__ float  g_y[(size_t)NN * 64];      // layer-1 output fp32 (attn_lin<2> input)
__device__ __half g_yh[(size_t)NPAD * 64];   // layer-1 output fp16 (GEMM2 A)
__device__ __half g_xh[(size_t)NPAD * 128];  // x fp16 (GEMM1 A)
__device__ __half g_W1h[128 * 256];
__device__ __half g_W2h[64 * 256];
__device__ float  g_Wa1[8 * 128];            // folded att vectors, layout [j][k]
__device__ float  g_Wa2[8 * 64];
__device__ float  g_a[(size_t)NN * 8];       // [0..3]=a_src, [4..7]=a_dst per head
__device__ int    g_counts[NN];
__device__ int    g_cursor[NN];
__device__ int    g_off[NN];
__device__ int    g_csrc[EAX];
__device__ int    g_total;
__device__ int    g_node1, g_node2;          // dynamic work counters (per layer)
__device__ int    g_is64;

__device__ __forceinline__ int edge_at(const void* ei, long long idx) {
    return g_is64 ? (int)((const long long*)ei)[idx]
                  : ((const int*)ei)[idx];
}

// ---------------------------------------------------------------------------
// prep: dtype detect, counter resets, fp16 conversions, attention folds.
// One launch, grid-stride over all independent work.
// ---------------------------------------------------------------------------
__global__ void __launch_bounds__(256) prep_kernel(
        const float* __restrict__ x,
        const float* __restrict__ W1, const float* __restrict__ W2,
        const float* __restrict__ as1, const float* __restrict__ ad1,
        const float* __restrict__ as2, const float* __restrict__ ad2,
        const void* __restrict__ ei, int Nn, int E) {
    int t = blockIdx.x * blockDim.x + threadIdx.x;
    int stride = gridDim.x * blockDim.x;

    if (t == 0) {
        g_total = 0; g_node1 = 0; g_node2 = 0;
        const long long* p = (const long long*)ei;
        int ns = (E < 256) ? E : 256;
        int ok64 = 1;
        for (int i = 0; i < ns; i++) {
            long long v = p[i];
            if (v < 0 || v >= (long long)Nn) { ok64 = 0; break; }
        }
        g_is64 = ok64;
    }

    for (int i = t; i < Nn; i += stride) { g_counts[i] = 0; g_cursor[i] = 0; }

    int nx = Nn * 64;   // x as float2 pairs
    for (int i = t; i < nx; i += stride) {
        float2 v = *(const float2*)(x + (size_t)i * 2);
        *(__half2*)(g_xh + (size_t)i * 2) = __floats2half2_rn(v.x, v.y);
    }

    for (int i = t; i < 128 * 256; i += stride) g_W1h[i] = __float2half(W1[i]);
    for (int i = t; i < 64 * 256;  i += stride) g_W2h[i] = __float2half(W2[i]);

    // fold: Wa[j][k] = sum_c W[k, h*64+c] * att[h, c]; 1536 outputs, float4 dots
    for (int i = t; i < 1536; i += stride) {
        if (i < 1024) {
            int k = i >> 3, j = i & 7, h = j & 3;
            const float4* w  = (const float4*)(W1 + (size_t)k * 256 + h * 64);
            const float4* av = (const float4*)(((j < 4) ? as1 : ad1) + h * 64);
            float s = 0.f;
#pragma unroll
            for (int c = 0; c < 16; c++) {
                float4 a = w[c], b = av[c];
                s += a.x * b.x + a.y * b.y + a.z * b.z + a.w * b.w;
            }
            g_Wa1[j * 128 + k] = s;
        } else {
            int i2 = i - 1024;
            int k = i2 >> 3, j = i2 & 7, h = j & 3;
            const float4* w  = (const float4*)(W2 + (size_t)k * 256 + h * 64);
            const float4* av = (const float4*)(((j < 4) ? as2 : ad2) + h * 64);
            float s = 0.f;
#pragma unroll
            for (int c = 0; c < 16; c++) {
                float4 a = w[c], b = av[c];
                s += a.x * b.x + a.y * b.y + a.z * b.z + a.w * b.w;
            }
            g_Wa2[j * 64 + k] = s;
        }
    }
}

// ---------------------------- CSR build ------------------------------------
__global__ void count_kernel(const void* __restrict__ ei, int E, int Nn) {
    int t = blockIdx.x * blockDim.x + threadIdx.x;
    if (t >= E + Nn) return;
    int d = (t < E) ? edge_at(ei, (long long)E + t) : (t - E);
    atomicAdd(&g_counts[d], 1);
}

__global__ void offsets_kernel(int Nn) {
    int t    = blockIdx.x * blockDim.x + threadIdx.x;
    int lane = threadIdx.x & 31;
    int c    = (t < Nn) ? g_counts[t] : 0;
    int incl = c;
#pragma unroll
    for (int off = 1; off < 32; off <<= 1) {
        int v = __shfl_up_sync(0xffffffffu, incl, off);
        if (lane >= off) incl += v;
    }
    int tot = __shfl_sync(0xffffffffu, incl, 31);
    int base = 0;
    if (lane == 31) base = atomicAdd(&g_total, tot);
    base = __shfl_sync(0xffffffffu, base, 31);
    if (t < Nn) g_off[t] = base + incl - c;
}

__global__ void scatter_kernel(const void* __restrict__ ei, int E, int Nn) {
    int t = blockIdx.x * blockDim.x + threadIdx.x;
    if (t >= E + Nn) return;
    int s, d;
    if (t < E) { s = edge_at(ei, t); d = edge_at(ei, (long long)E + t); }
    else       { s = d = t - E; }
    int pos = atomicAdd(&g_cursor[d], 1);
    g_csrc[g_off[d] + pos] = s;
}

// ---------------------------------------------------------------------------
// wmma GEMM: A[M,K] fp16 @ W[K,256] fp16 -> g_hh fp16 (fp32 accumulate,
// staged through smem).  LAYER=1: A=g_xh (K=128); LAYER=2: A=g_yh (K=64).
// ---------------------------------------------------------------------------
template <int LAYER>
__global__ void __launch_bounds__(256) wmma_gemm() {
    constexpr int K = (LAYER == 1) ? 128 : 64;
    const __half* A  = (LAYER == 1) ? g_xh  : g_yh;
    const __half* Wh = (LAYER == 1) ? g_W1h : g_W2h;

    __shared__ float st[64 * 128];

    int wid  = threadIdx.x >> 5;
    int rw   = (wid & 3) * 16;
    int cw   = (wid >> 2) * 64;
    int row0 = blockIdx.x * 64 + rw;
    int colb = blockIdx.y * 128;

    wmma::fragment<wmma::accumulator, 16, 16, 16, float> c[4];
#pragma unroll
    for (int i = 0; i < 4; i++) wmma::fill_fragment(c[i], 0.f);

#pragma unroll
    for (int k = 0; k < K; k += 16) {
        wmma::fragment<wmma::matrix_a, 16, 16, 16, __half, wmma::row_major> a;
        wmma::load_matrix_sync(a, A + (size_t)row0 * K + k, K);
#pragma unroll
        for (int i = 0; i < 4; i++) {
            wmma::fragment<wmma::matrix_b, 16, 16, 16, __half, wmma::row_major> b;
            wmma::load_matrix_sync(b, Wh + (size_t)k * 256 + colb + cw + i * 16, 256);
            wmma::mma_sync(c[i], a, b, c[i]);
        }
    }
#pragma unroll
    for (int i = 0; i < 4; i++)
        wmma::store_matrix_sync(st + rw * 128 + cw + i * 16, c[i], 128,
                                wmma::mem_row_major);
    __syncthreads();

    int rbase = blockIdx.x * 64;
    for (int idx = threadIdx.x; idx < 64 * 64; idx += 256) {
        int r = idx >> 6, cp = idx & 63;
        float2 f = *(float2*)(st + r * 128 + cp * 2);
        *(__half2*)(g_hh + (size_t)(rbase + r) * 256 + colb + cp * 2) =
            __floats2half2_rn(f.x, f.y);
    }
}

// ---------------------------------------------------------------------------
// Attention coefficients: g_a[n][j] = X[n,:] . Wa[j,:]  (fp32, exact).
// ---------------------------------------------------------------------------
template <int LAYER>
__global__ void __launch_bounds__(256) attn_lin(const float* __restrict__ Xin, int Nn) {
    constexpr int K  = (LAYER == 1) ? 128 : 64;
    constexpr int NI = K / 32;
    const float* Wa = (LAYER == 1) ? g_Wa1 : g_Wa2;
    const float* X  = (LAYER == 1) ? Xin   : g_y;

    __shared__ float sWa[8 * K];
    for (int i = threadIdx.x; i < 8 * K; i += 256) sWa[i] = Wa[i];
    __syncthreads();

    int warp = (blockIdx.x * blockDim.x + threadIdx.x) >> 5;
    int lane = threadIdx.x & 31;
    if (warp >= Nn) return;
    int n = warp;

    float xv[NI];
#pragma unroll
    for (int i = 0; i < NI; i++) xv[i] = X[(size_t)n * K + i * 32 + lane];

    float d[8];
#pragma unroll
    for (int j = 0; j < 8; j++) {
        float s = 0.f;
#pragma unroll
        for (int i = 0; i < NI; i++)
            s = fmaf(xv[i], sWa[j * K + i * 32 + lane], s);
#pragma unroll
        for (int off = 16; off; off >>= 1)
            s += __shfl_xor_sync(0xffffffffu, s, off);
        d[j] = s;
    }
    if (lane == 0) {
        float4* out = (float4*)(g_a + (size_t)n * 8);
        out[0] = make_float4(d[0], d[1], d[2], d[3]);
        out[1] = make_float4(d[4], d[5], d[6], d[7]);
    }
}

// ---------------------------------------------------------------------------
// GAT aggregation, single pass, fp16 gather, x2 unrolled, DYNAMIC node
// scheduling: each warp fetches 4-node chunks from a global counter to
// balance degree skew.  Lane l covers cols [8l, 8l+8), head = l>>3.
// ---------------------------------------------------------------------------
template <bool RELU, bool TO_Y>
__global__ void __launch_bounds__(256) gat_aggregate(const float* __restrict__ bias,
                                                     float* __restrict__ outp, int Nn) {
    int lane = threadIdx.x & 31;
    int* ctr = TO_Y ? &g_node1 : &g_node2;

    for (;;) {
        int base = 0;
        if (lane == 0) base = atomicAdd(ctr, 4);
        base = __shfl_sync(0xffffffffu, base, 0);
        if (base >= Nn) break;
        int lim = (base + 4 < Nn) ? base + 4 : Nn;

        for (int n = base; n < lim; n++) {
            int beg = g_off[n];
            int cnt = g_counts[n];
            int h   = lane >> 3;
            int sub = lane & 7;

            float adv = g_a[(size_t)n * 8 + 4 + h];

            float acc[8];
#pragma unroll
            for (int i = 0; i < 8; i++) acc[i] = 0.f;
            float sw = 0.f;

            int j = 0;
            for (; j + 2 <= cnt; j += 2) {
                int s0 = g_csrc[beg + j];
                int s1 = g_csrc[beg + j + 1];
                float e0 = __ldg(g_a + (size_t)s0 * 8 + h) + adv;
                float e1 = __ldg(g_a + (size_t)s1 * 8 + h) + adv;
                float4 r0 = *((const float4*)(g_hh + (size_t)s0 * 256) + lane);
                float4 r1 = *((const float4*)(g_hh + (size_t)s1 * 256) + lane);
                e0 = (e0 > 0.f) ? e0 : 0.2f * e0;
                e1 = (e1 > 0.f) ? e1 : 0.2f * e1;
                float w0 = __expf(e0), w1 = __expf(e1);
                sw += w0 + w1;
                {
                    const __half2* hp = (const __half2*)&r0;
                    float2 f0 = __half22float2(hp[0]), f1 = __half22float2(hp[1]);
                    float2 f2 = __half22float2(hp[2]), f3 = __half22float2(hp[3]);
                    acc[0] = fmaf(w0, f0.x, acc[0]); acc[1] = fmaf(w0, f0.y, acc[1]);
                    acc[2] = fmaf(w0, f1.x, acc[2]); acc[3] = fmaf(w0, f1.y, acc[3]);
                    acc[4] = fmaf(w0, f2.x, acc[4]); acc[5] = fmaf(w0, f2.y, acc[5]);
                    acc[6] = fmaf(w0, f3.x, acc[6]); acc[7] = fmaf(w0, f3.y, acc[7]);
                }
                {
                    const __half2* hp = (const __half2*)&r1;
                    float2 f0 = __half22float2(hp[0]), f1 = __half22float2(hp[1]);
                    float2 f2 = __half22float2(hp[2]), f3 = __half22float2(hp[3]);
                    acc[0] = fmaf(w1, f0.x, acc[0]); acc[1] = fmaf(w1, f0.y, acc[1]);
                    acc[2] = fmaf(w1, f1.x, acc[2]); acc[3] = fmaf(w1, f1.y, acc[3]);
                    acc[4] = fmaf(w1, f2.x, acc[4]); acc[5] = fmaf(w1, f2.y, acc[5]);
                    acc[6] = fmaf(w1, f3.x, acc[6]); acc[7] = fmaf(w1, f3.y, acc[7]);
                }
            }
            if (j < cnt) {
                int s = g_csrc[beg + j];
                float e = __ldg(g_a + (size_t)s * 8 + h) + adv;
                e = (e > 0.f) ? e : 0.2f * e;
                float w = __expf(e);
                sw += w;
                float4 raw = *((const float4*)(g_hh + (size_t)s * 256) + lane);
                const __half2* hp = (const __half2*)&raw;
                float2 f0 = __half22float2(hp[0]), f1 = __half22float2(hp[1]);
                float2 f2 = __half22float2(hp[2]), f3 = __half22float2(hp[3]);
                acc[0] = fmaf(w, f0.x, acc[0]); acc[1] = fmaf(w, f0.y, acc[1]);
                acc[2] = fmaf(w, f1.x, acc[2]); acc[3] = fmaf(w, f1.y, acc[3]);
                acc[4] = fmaf(w, f2.x, acc[4]); acc[5] = fmaf(w, f2.y, acc[5]);
                acc[6] = fmaf(w, f3.x, acc[6]); acc[7] = fmaf(w, f3.y, acc[7]);
            }

            float r = 1.f / (sw + 1e-16f);
#pragma unroll
            for (int i = 0; i < 8; i++) {
                acc[i] *= r;
                acc[i] += __shfl_xor_sync(0xffffffffu, acc[i], 8);
                acc[i] += __shfl_xor_sync(0xffffffffu, acc[i], 16);
            }

            if (h == 0) {   // lanes 0..7: 4-head sums for cols [8*sub, 8*sub+8)
                int c0 = sub * 8;
                float4 b0 = *(const float4*)(bias + c0);
                float4 b1 = *(const float4*)(bias + c0 + 4);
                float4 o0, o1;
                o0.x = 0.25f * acc[0] + b0.x;  o0.y = 0.25f * acc[1] + b0.y;
                o0.z = 0.25f * acc[2] + b0.z;  o0.w = 0.25f * acc[3] + b0.w;
                o1.x = 0.25f * acc[4] + b1.x;  o1.y = 0.25f * acc[5] + b1.y;
                o1.z = 0.25f * acc[6] + b1.z;  o1.w = 0.25f * acc[7] + b1.w;
                if (RELU) {
                    o0.x = fmaxf(o0.x, 0.f); o0.y = fmaxf(o0.y, 0.f);
                    o0.z = fmaxf(o0.z, 0.f); o0.w = fmaxf(o0.w, 0.f);
                    o1.x = fmaxf(o1.x, 0.f); o1.y = fmaxf(o1.y, 0.f);
                    o1.z = fmaxf(o1.z, 0.f); o1.w = fmaxf(o1.w, 0.f);
                }
                float* out = TO_Y ? g_y : outp;
                *(float4*)(out + (size_t)n * 64 + c0)     = o0;
                *(float4*)(out + (size_t)n * 64 + c0 + 4) = o1;
                if (TO_Y) {  // fp16 shadow for GEMM2's A operand
                    __half2* yh = (__half2*)(g_yh + (size_t)n * 64 + c0);
                    yh[0] = __floats2half2_rn(o0.x, o0.y);
                    yh[1] = __floats2half2_rn(o0.z, o0.w);
                    yh[2] = __floats2half2_rn(o1.x, o1.y);
                    yh[3] = __floats2half2_rn(o1.z, o1.w);
                }
            }
        }
    }
}

// ---------------------------------------------------------------------------
extern "C" void kernel_launch(void* const* d_in, const int* in_sizes, int n_in,
                              void* d_out, int out_size) {
    const float* x   = (const float*)d_in[0];
    const void*  ei  = d_in[1];
    const float* W1  = (const float*)d_in[2];
    const float* as1 = (const float*)d_in[3];
    const float* ad1 = (const float*)d_in[4];
    const float* b1  = (const float*)d_in[5];
    const float* W2  = (const float*)d_in[6];
    const float* as2 = (const float*)d_in[7];
    const float* ad2 = (const float*)d_in[8];
    const float* b2  = (const float*)d_in[9];

    int N  = in_sizes[0] / 128;
    int E  = in_sizes[1] / 2;
    int EA = E + N;

    // launch 0: fused preamble
    prep_kernel<<<256, 256>>>(x, W1, W2, as1, ad1, as2, ad2, ei, N, E);
    // launches 1-3: CSR build (launch 3 = scatter, lands in ncu's window)
    count_kernel<<<(EA + 255) / 256, 256>>>(ei, E, N);
    offsets_kernel<<<(N + 255) / 256, 256>>>(N);
    scatter_kernel<<<(EA + 255) / 256, 256>>>(ei, E, N);

    int nodeWarpBlocks = (N + 7) / 8;   // 256 thr = 8 warps/block
    dim3 ggrid(NPAD / 64, 2);

    // ---- layer 1 ----
    wmma_gemm<1><<<ggrid, 256>>>();
    attn_lin<1><<<nodeWarpBlocks, 256>>>(x, N);
    gat_aggregate<true, true><<<592, 256>>>(b1, nullptr, N);

    // ---- layer 2 ----
    wmma_gemm<2><<<ggrid, 256>>>();
    attn_lin<2><<<nodeWarpBlocks, 256>>>(nullptr, N);
    gat_aggregate<false, false><<<592, 256>>>(b2, (float*)d_out, N);
}

// round 11
// speedup vs baseline: 1.1447x; 1.1447x over previous
#include <cuda_runtime.h>
#include <cuda_fp16.h>
#include <mma.h>

using namespace nvcuda;

// Problem constants (fixed by the dataset)
#define NN 50000
#define NPAD 50048              // 782 * 64 (wmma M-tile padding)
#define EE 800000
#define EAX (EE + NN)           // edges + self loops

// ---------------- scratch (device globals; no allocations allowed) ----------
__device__ __half g_hh[(size_t)NPAD * 256];  // fp16 features (wmma writes, aggregate reads)
__device__ float  g_y[(size_t)NN * 64];      // layer-1 output fp32 (attn_lin<2> input)
__device__ __half g_yh[(size_t)NPAD * 64];   // layer-1 output fp16 (GEMM2 A)
__device__ __half g_xh[(size_t)NPAD * 128];  // x fp16 (GEMM1 A)
__device__ __half g_W1h[128 * 256];
__device__ __half g_W2h[64 * 256];
__device__ float  g_Wa1[8 * 128];            // folded att vectors, layout [j][k]
__device__ float  g_Wa2[8 * 64];
__device__ float  g_a[(size_t)NN * 8];       // [0..3]=a_src, [4..7]=a_dst per head
__device__ int    g_counts[NN];
__device__ int    g_cursor[NN];
__device__ int    g_off[NN];
__device__ int    g_csrc[EAX];
__device__ int    g_total;
__device__ int    g_is64;

__device__ __forceinline__ int edge_at(const void* ei, long long idx) {
    return g_is64 ? (int)((const long long*)ei)[idx]
                  : ((const int*)ei)[idx];
}

// ---------------------------------------------------------------------------
// prep: dtype detect, counter resets, fp16 conversions, attention folds.
// ---------------------------------------------------------------------------
__global__ void __launch_bounds__(256) prep_kernel(
        const float* __restrict__ x,
        const float* __restrict__ W1, const float* __restrict__ W2,
        const float* __restrict__ as1, const float* __restrict__ ad1,
        const float* __restrict__ as2, const float* __restrict__ ad2,
        const void* __restrict__ ei, int Nn, int E) {
    int t = blockIdx.x * blockDim.x + threadIdx.x;
    int stride = gridDim.x * blockDim.x;

    if (t == 0) {
        g_total = 0;
        const long long* p = (const long long*)ei;
        int ns = (E < 256) ? E : 256;
        int ok64 = 1;
        for (int i = 0; i < ns; i++) {
            long long v = p[i];
            if (v < 0 || v >= (long long)Nn) { ok64 = 0; break; }
        }
        g_is64 = ok64;
    }

    for (int i = t; i < Nn; i += stride) { g_counts[i] = 0; g_cursor[i] = 0; }

    int nx = Nn * 64;   // x as float2 pairs
    for (int i = t; i < nx; i += stride) {
        float2 v = *(const float2*)(x + (size_t)i * 2);
        *(__half2*)(g_xh + (size_t)i * 2) = __floats2half2_rn(v.x, v.y);
    }

    for (int i = t; i < 128 * 256; i += stride) g_W1h[i] = __float2half(W1[i]);
    for (int i = t; i < 64 * 256;  i += stride) g_W2h[i] = __float2half(W2[i]);

    // fold: Wa[j][k] = sum_c W[k, h*64+c] * att[h, c]; 1536 outputs, float4 dots
    for (int i = t; i < 1536; i += stride) {
        if (i < 1024) {
            int k = i >> 3, j = i & 7, h = j & 3;
            const float4* w  = (const float4*)(W1 + (size_t)k * 256 + h * 64);
            const float4* av = (const float4*)(((j < 4) ? as1 : ad1) + h * 64);
            float s = 0.f;
#pragma unroll
            for (int c = 0; c < 16; c++) {
                float4 a = w[c], b = av[c];
                s += a.x * b.x + a.y * b.y + a.z * b.z + a.w * b.w;
            }
            g_Wa1[j * 128 + k] = s;
        } else {
            int i2 = i - 1024;
            int k = i2 >> 3, j = i2 & 7, h = j & 3;
            const float4* w  = (const float4*)(W2 + (size_t)k * 256 + h * 64);
            const float4* av = (const float4*)(((j < 4) ? as2 : ad2) + h * 64);
            float s = 0.f;
#pragma unroll
            for (int c = 0; c < 16; c++) {
                float4 a = w[c], b = av[c];
                s += a.x * b.x + a.y * b.y + a.z * b.z + a.w * b.w;
            }
            g_Wa2[j * 64 + k] = s;
        }
    }
}

// ---------------------------- CSR build ------------------------------------
__global__ void count_kernel(const void* __restrict__ ei, int E, int Nn) {
    int t = blockIdx.x * blockDim.x + threadIdx.x;
    if (t >= E + Nn) return;
    int d = (t < E) ? edge_at(ei, (long long)E + t) : (t - E);
    atomicAdd(&g_counts[d], 1);
}

__global__ void offsets_kernel(int Nn) {
    int t    = blockIdx.x * blockDim.x + threadIdx.x;
    int lane = threadIdx.x & 31;
    int c    = (t < Nn) ? g_counts[t] : 0;
    int incl = c;
#pragma unroll
    for (int off = 1; off < 32; off <<= 1) {
        int v = __shfl_up_sync(0xffffffffu, incl, off);
        if (lane >= off) incl += v;
    }
    int tot = __shfl_sync(0xffffffffu, incl, 31);
    int base = 0;
    if (lane == 31) base = atomicAdd(&g_total, tot);
    base = __shfl_sync(0xffffffffu, base, 31);
    if (t < Nn) g_off[t] = base + incl - c;
}

__global__ void scatter_kernel(const void* __restrict__ ei, int E, int Nn) {
    int t = blockIdx.x * blockDim.x + threadIdx.x;
    if (t >= E + Nn) return;
    int s, d;
    if (t < E) { s = edge_at(ei, t); d = edge_at(ei, (long long)E + t); }
    else       { s = d = t - E; }
    int pos = atomicAdd(&g_cursor[d], 1);
    g_csrc[g_off[d] + pos] = s;
}

// ---------------------------------------------------------------------------
// wmma GEMM: A[M,K] fp16 @ W[K,256] fp16 -> g_hh fp16 (fp32 accumulate,
// staged through smem).  LAYER=1: A=g_xh (K=128); LAYER=2: A=g_yh (K=64).
// ---------------------------------------------------------------------------
template <int LAYER>
__global__ void __launch_bounds__(256) wmma_gemm() {
    constexpr int K = (LAYER == 1) ? 128 : 64;
    const __half* A  = (LAYER == 1) ? g_xh  : g_yh;
    const __half* Wh = (LAYER == 1) ? g_W1h : g_W2h;

    __shared__ float st[64 * 128];

    int wid  = threadIdx.x >> 5;
    int rw   = (wid & 3) * 16;
    int cw   = (wid >> 2) * 64;
    int row0 = blockIdx.x * 64 + rw;
    int colb = blockIdx.y * 128;

    wmma::fragment<wmma::accumulator, 16, 16, 16, float> c[4];
#pragma unroll
    for (int i = 0; i < 4; i++) wmma::fill_fragment(c[i], 0.f);

#pragma unroll
    for (int k = 0; k < K; k += 16) {
        wmma::fragment<wmma::matrix_a, 16, 16, 16, __half, wmma::row_major> a;
        wmma::load_matrix_sync(a, A + (size_t)row0 * K + k, K);
#pragma unroll
        for (int i = 0; i < 4; i++) {
            wmma::fragment<wmma::matrix_b, 16, 16, 16, __half, wmma::row_major> b;
            wmma::load_matrix_sync(b, Wh + (size_t)k * 256 + colb + cw + i * 16, 256);
            wmma::mma_sync(c[i], a, b, c[i]);
        }
    }
#pragma unroll
    for (int i = 0; i < 4; i++)
        wmma::store_matrix_sync(st + rw * 128 + cw + i * 16, c[i], 128,
                                wmma::mem_row_major);
    __syncthreads();

    int rbase = blockIdx.x * 64;
    for (int idx = threadIdx.x; idx < 64 * 64; idx += 256) {
        int r = idx >> 6, cp = idx & 63;
        float2 f = *(float2*)(st + r * 128 + cp * 2);
        *(__half2*)(g_hh + (size_t)(rbase + r) * 256 + colb + cp * 2) =
            __floats2half2_rn(f.x, f.y);
    }
}

// ---------------------------------------------------------------------------
// Attention coefficients: g_a[n][j] = X[n,:] . Wa[j,:]  (fp32, exact).
// ---------------------------------------------------------------------------
template <int LAYER>
__global__ void __launch_bounds__(256) attn_lin(const float* __restrict__ Xin, int Nn) {
    constexpr int K  = (LAYER == 1) ? 128 : 64;
    constexpr int NI = K / 32;
    const float* Wa = (LAYER == 1) ? g_Wa1 : g_Wa2;
    const float* X  = (LAYER == 1) ? Xin   : g_y;

    __shared__ float sWa[8 * K];
    for (int i = threadIdx.x; i < 8 * K; i += 256) sWa[i] = Wa[i];
    __syncthreads();

    int warp = (blockIdx.x * blockDim.x + threadIdx.x) >> 5;
    int lane = threadIdx.x & 31;
    if (warp >= Nn) return;
    int n = warp;

    float xv[NI];
#pragma unroll
    for (int i = 0; i < NI; i++) xv[i] = X[(size_t)n * K + i * 32 + lane];

    float d[8];
#pragma unroll
    for (int j = 0; j < 8; j++) {
        float s = 0.f;
#pragma unroll
        for (int i = 0; i < NI; i++)
            s = fmaf(xv[i], sWa[j * K + i * 32 + lane], s);
#pragma unroll
        for (int off = 16; off; off >>= 1)
            s += __shfl_xor_sync(0xffffffffu, s, off);
        d[j] = s;
    }
    if (lane == 0) {
        float4* out = (float4*)(g_a + (size_t)n * 8);
        out[0] = make_float4(d[0], d[1], d[2], d[3]);
        out[1] = make_float4(d[4], d[5], d[6], d[7]);
    }
}

// ---------------------------------------------------------------------------
// GAT aggregation: STATIC warp-per-node (R9 regression reverted) with
// warp-batched edge ids: 32 ids per coalesced LDG, broadcast via shfl.
// Critical path per edge: shfl (reg) -> gather LDGs, instead of LDG -> LDG.
// Lane l covers cols [8l, 8l+8), head = l>>3.
// ---------------------------------------------------------------------------
template <bool RELU, bool TO_Y>
__global__ void __launch_bounds__(256) gat_aggregate(const float* __restrict__ bias,
                                                     float* __restrict__ outp, int Nn) {
    int warp = (blockIdx.x * blockDim.x + threadIdx.x) >> 5;
    int lane = threadIdx.x & 31;
    if (warp >= Nn) return;
    int n    = warp;
    int beg  = g_off[n];
    int cnt  = g_counts[n];
    int h    = lane >> 3;
    int sub  = lane & 7;

    float adv = g_a[(size_t)n * 8 + 4 + h];

    float acc[8];
#pragma unroll
    for (int i = 0; i < 8; i++) acc[i] = 0.f;
    float sw = 0.f;

    for (int jb = 0; jb < cnt; jb += 32) {
        int m  = cnt - jb; if (m > 32) m = 32;
        int sv = (jb + lane < cnt) ? g_csrc[beg + jb + lane] : 0;

        int k = 0;
        for (; k + 2 <= m; k += 2) {
            int s0 = __shfl_sync(0xffffffffu, sv, k);
            int s1 = __shfl_sync(0xffffffffu, sv, k + 1);
            float e0 = __ldg(g_a + (size_t)s0 * 8 + h) + adv;
            float e1 = __ldg(g_a + (size_t)s1 * 8 + h) + adv;
            float4 r0 = *((const float4*)(g_hh + (size_t)s0 * 256) + lane);
            float4 r1 = *((const float4*)(g_hh + (size_t)s1 * 256) + lane);
            e0 = (e0 > 0.f) ? e0 : 0.2f * e0;
            e1 = (e1 > 0.f) ? e1 : 0.2f * e1;
            float w0 = __expf(e0), w1 = __expf(e1);
            sw += w0 + w1;
            {
                const __half2* hp = (const __half2*)&r0;
                float2 f0 = __half22float2(hp[0]), f1 = __half22float2(hp[1]);
                float2 f2 = __half22float2(hp[2]), f3 = __half22float2(hp[3]);
                acc[0] = fmaf(w0, f0.x, acc[0]); acc[1] = fmaf(w0, f0.y, acc[1]);
                acc[2] = fmaf(w0, f1.x, acc[2]); acc[3] = fmaf(w0, f1.y, acc[3]);
                acc[4] = fmaf(w0, f2.x, acc[4]); acc[5] = fmaf(w0, f2.y, acc[5]);
                acc[6] = fmaf(w0, f3.x, acc[6]); acc[7] = fmaf(w0, f3.y, acc[7]);
            }
            {
                const __half2* hp = (const __half2*)&r1;
                float2 f0 = __half22float2(hp[0]), f1 = __half22float2(hp[1]);
                float2 f2 = __half22float2(hp[2]), f3 = __half22float2(hp[3]);
                acc[0] = fmaf(w1, f0.x, acc[0]); acc[1] = fmaf(w1, f0.y, acc[1]);
                acc[2] = fmaf(w1, f1.x, acc[2]); acc[3] = fmaf(w1, f1.y, acc[3]);
                acc[4] = fmaf(w1, f2.x, acc[4]); acc[5] = fmaf(w1, f2.y, acc[5]);
                acc[6] = fmaf(w1, f3.x, acc[6]); acc[7] = fmaf(w1, f3.y, acc[7]);
            }
        }
        if (k < m) {
            int s = __shfl_sync(0xffffffffu, sv, k);
            float e = __ldg(g_a + (size_t)s * 8 + h) + adv;
            e = (e > 0.f) ? e : 0.2f * e;
            float w = __expf(e);
            sw += w;
            float4 raw = *((const float4*)(g_hh + (size_t)s * 256) + lane);
            const __half2* hp = (const __half2*)&raw;
            float2 f0 = __half22float2(hp[0]), f1 = __half22float2(hp[1]);
            float2 f2 = __half22float2(hp[2]), f3 = __half22float2(hp[3]);
            acc[0] = fmaf(w, f0.x, acc[0]); acc[1] = fmaf(w, f0.y, acc[1]);
            acc[2] = fmaf(w, f1.x, acc[2]); acc[3] = fmaf(w, f1.y, acc[3]);
            acc[4] = fmaf(w, f2.x, acc[4]); acc[5] = fmaf(w, f2.y, acc[5]);
            acc[6] = fmaf(w, f3.x, acc[6]); acc[7] = fmaf(w, f3.y, acc[7]);
        }
    }

    float r = 1.f / (sw + 1e-16f);
#pragma unroll
    for (int i = 0; i < 8; i++) {
        acc[i] *= r;
        acc[i] += __shfl_xor_sync(0xffffffffu, acc[i], 8);
        acc[i] += __shfl_xor_sync(0xffffffffu, acc[i], 16);
    }

    if (h == 0) {   // lanes 0..7: 4-head sums for cols [8*sub, 8*sub+8)
        int c0 = sub * 8;
        float4 b0 = *(const float4*)(bias + c0);
        float4 b1 = *(const float4*)(bias + c0 + 4);
        float4 o0, o1;
        o0.x = 0.25f * acc[0] + b0.x;  o0.y = 0.25f * acc[1] + b0.y;
        o0.z = 0.25f * acc[2] + b0.z;  o0.w = 0.25f * acc[3] + b0.w;
        o1.x = 0.25f * acc[4] + b1.x;  o1.y = 0.25f * acc[5] + b1.y;
        o1.z = 0.25f * acc[6] + b1.z;  o1.w = 0.25f * acc[7] + b1.w;
        if (RELU) {
            o0.x = fmaxf(o0.x, 0.f); o0.y = fmaxf(o0.y, 0.f);
            o0.z = fmaxf(o0.z, 0.f); o0.w = fmaxf(o0.w, 0.f);
            o1.x = fmaxf(o1.x, 0.f); o1.y = fmaxf(o1.y, 0.f);
            o1.z = fmaxf(o1.z, 0.f); o1.w = fmaxf(o1.w, 0.f);
        }
        float* out = TO_Y ? g_y : outp;
        *(float4*)(out + (size_t)n * 64 + c0)     = o0;
        *(float4*)(out + (size_t)n * 64 + c0 + 4) = o1;
        if (TO_Y) {  // fp16 shadow for GEMM2's A operand
            __half2* yh = (__half2*)(g_yh + (size_t)n * 64 + c0);
            yh[0] = __floats2half2_rn(o0.x, o0.y);
            yh[1] = __floats2half2_rn(o0.z, o0.w);
            yh[2] = __floats2half2_rn(o1.x, o1.y);
            yh[3] = __floats2half2_rn(o1.z, o1.w);
        }
    }
}

// ---------------------------------------------------------------------------
extern "C" void kernel_launch(void* const* d_in, const int* in_sizes, int n_in,
                              void* d_out, int out_size) {
    const float* x   = (const float*)d_in[0];
    const void*  ei  = d_in[1];
    const float* W1  = (const float*)d_in[2];
    const float* as1 = (const float*)d_in[3];
    const float* ad1 = (const float*)d_in[4];
    const float* b1  = (const float*)d_in[5];
    const float* W2  = (const float*)d_in[6];
    const float* as2 = (const float*)d_in[7];
    const float* ad2 = (const float*)d_in[8];
    const float* b2  = (const float*)d_in[9];

    int N  = in_sizes[0] / 128;
    int E  = in_sizes[1] / 2;
    int EA = E + N;

    int nodeWarpBlocks = (N + 7) / 8;   // 256 thr = 8 warps/block
    dim3 ggrid(NPAD / 64, 2);

    // launches 0-2: preamble + CSR counts/offsets
    prep_kernel<<<256, 256>>>(x, W1, W2, as1, ad1, as2, ad2, ei, N, E);
    count_kernel<<<(EA + 255) / 256, 256>>>(ei, E, N);
    offsets_kernel<<<(N + 255) / 256, 256>>>(N);
    // launch 3 (= ncu capture slot): layer-1 GEMM
    wmma_gemm<1><<<ggrid, 256>>>();
    // launch 4: scatter (independent of gemm; must precede aggregate)
    scatter_kernel<<<(EA + 255) / 256, 256>>>(ei, E, N);

    // ---- layer 1 ----
    attn_lin<1><<<nodeWarpBlocks, 256>>>(x, N);
    gat_aggregate<true, true><<<nodeWarpBlocks, 256>>>(b1, nullptr, N);

    // ---- layer 2 ----
    wmma_gemm<2><<<ggrid, 256>>>();
    attn_lin<2><<<nodeWarpBlocks, 256>>>(nullptr, N);
    gat_aggregate<false, false><<<nodeWarpBlocks, 256>>>(b2, (float*)d_out, N);
}

// round 12
// speedup vs baseline: 1.5228x; 1.3303x over previous
#include <cuda_runtime.h>
#include <cuda_fp16.h>
#include <mma.h>

using namespace nvcuda;

// Problem constants (fixed by the dataset)
#define NN 50000
#define NPAD 50048              // 782 * 64 (wmma M-tile padding)
#define EE 800000
#define EAX (EE + NN)           // edges + self loops

// ---------------- scratch (device globals; no allocations allowed) ----------
__device__ __half g_hh[(size_t)NPAD * 256];  // fp16 features (wmma writes, aggregate reads)
__device__ float  g_y[(size_t)NN * 64];      // layer-1 output fp32 (attn_lin<2> input)
__device__ __half g_yh[(size_t)NPAD * 64];   // layer-1 output fp16 (GEMM2 A)
__device__ __half g_xh[(size_t)NPAD * 128];  // x fp16 (GEMM1 A)
__device__ __half g_W1h[128 * 256];
__device__ __half g_W2h[64 * 256];
__device__ float  g_Wa1[8 * 128];            // folded att vectors, layout [j][k]
__device__ float  g_Wa2[8 * 64];
__device__ float  g_a[(size_t)NN * 8];       // [0..3]=a_src, [4..7]=a_dst per head
__device__ int    g_counts[NN];
__device__ int    g_cursor[NN];
__device__ int    g_off[NN];
__device__ int    g_csrc[EAX];
__device__ int    g_total;
__device__ int    g_is64;

__device__ __forceinline__ int edge_at(const void* ei, long long idx) {
    return g_is64 ? (int)((const long long*)ei)[idx]
                  : ((const int*)ei)[idx];
}

// ---------------------------------------------------------------------------
// prep: dtype detect, counter resets, fp16 conversions, attention folds.
// ---------------------------------------------------------------------------
__global__ void __launch_bounds__(256) prep_kernel(
        const float* __restrict__ x,
        const float* __restrict__ W1, const float* __restrict__ W2,
        const float* __restrict__ as1, const float* __restrict__ ad1,
        const float* __restrict__ as2, const float* __restrict__ ad2,
        const void* __restrict__ ei, int Nn, int E) {
    int t = blockIdx.x * blockDim.x + threadIdx.x;
    int stride = gridDim.x * blockDim.x;

    if (t == 0) {
        g_total = 0;
        const long long* p = (const long long*)ei;
        int ns = (E < 256) ? E : 256;
        int ok64 = 1;
        for (int i = 0; i < ns; i++) {
            long long v = p[i];
            if (v < 0 || v >= (long long)Nn) { ok64 = 0; break; }
        }
        g_is64 = ok64;
    }

    for (int i = t; i < Nn; i += stride) { g_counts[i] = 0; g_cursor[i] = 0; }

    int nx = Nn * 64;   // x as float2 pairs
    for (int i = t; i < nx; i += stride) {
        float2 v = *(const float2*)(x + (size_t)i * 2);
        *(__half2*)(g_xh + (size_t)i * 2) = __floats2half2_rn(v.x, v.y);
    }

    for (int i = t; i < 128 * 256; i += stride) g_W1h[i] = __float2half(W1[i]);
    for (int i = t; i < 64 * 256;  i += stride) g_W2h[i] = __float2half(W2[i]);

    // fold: Wa[j][k] = sum_c W[k, h*64+c] * att[h, c]; 1536 outputs, float4 dots
    for (int i = t; i < 1536; i += stride) {
        if (i < 1024) {
            int k = i >> 3, j = i & 7, h = j & 3;
            const float4* w  = (const float4*)(W1 + (size_t)k * 256 + h * 64);
            const float4* av = (const float4*)(((j < 4) ? as1 : ad1) + h * 64);
            float s = 0.f;
#pragma unroll
            for (int c = 0; c < 16; c++) {
                float4 a = w[c], b = av[c];
                s += a.x * b.x + a.y * b.y + a.z * b.z + a.w * b.w;
            }
            g_Wa1[j * 128 + k] = s;
        } else {
            int i2 = i - 1024;
            int k = i2 >> 3, j = i2 & 7, h = j & 3;
            const float4* w  = (const float4*)(W2 + (size_t)k * 256 + h * 64);
            const float4* av = (const float4*)(((j < 4) ? as2 : ad2) + h * 64);
            float s = 0.f;
#pragma unroll
            for (int c = 0; c < 16; c++) {
                float4 a = w[c], b = av[c];
                s += a.x * b.x + a.y * b.y + a.z * b.z + a.w * b.w;
            }
            g_Wa2[j * 64 + k] = s;
        }
    }
}

// ---------------------------- CSR build ------------------------------------
__global__ void count_kernel(const void* __restrict__ ei, int E, int Nn) {
    int t = blockIdx.x * blockDim.x + threadIdx.x;
    if (t >= E + Nn) return;
    int d = (t < E) ? edge_at(ei, (long long)E + t) : (t - E);
    atomicAdd(&g_counts[d], 1);
}

__global__ void offsets_kernel(int Nn) {
    int t    = blockIdx.x * blockDim.x + threadIdx.x;
    int lane = threadIdx.x & 31;
    int c    = (t < Nn) ? g_counts[t] : 0;
    int incl = c;
#pragma unroll
    for (int off = 1; off < 32; off <<= 1) {
        int v = __shfl_up_sync(0xffffffffu, incl, off);
        if (lane >= off) incl += v;
    }
    int tot = __shfl_sync(0xffffffffu, incl, 31);
    int base = 0;
    if (lane == 31) base = atomicAdd(&g_total, tot);
    base = __shfl_sync(0xffffffffu, base, 31);
    if (t < Nn) g_off[t] = base + incl - c;
}

__global__ void scatter_kernel(const void* __restrict__ ei, int E, int Nn) {
    int t = blockIdx.x * blockDim.x + threadIdx.x;
    if (t >= E + Nn) return;
    int s, d;
    if (t < E) { s = edge_at(ei, t); d = edge_at(ei, (long long)E + t); }
    else       { s = d = t - E; }
    int pos = atomicAdd(&g_cursor[d], 1);
    g_csrc[g_off[d] + pos] = s;
}

// ---------------------------------------------------------------------------
// wmma GEMM, smem-staged: A[M,K] fp16 @ W[K,256] fp16 -> g_hh fp16.
// A tile (64 x K) staged once; W tile staged in 64-row K-chunks.  Fragments
// load from padded shared (LDSM), not global.  Epilogue fp32 tile aliases
// the staging buffer.  LAYER=1: A=g_xh (K=128); LAYER=2: A=g_yh (K=64).
// ---------------------------------------------------------------------------
template <int LAYER>
__global__ void __launch_bounds__(256) wmma_gemm() {
    constexpr int K   = (LAYER == 1) ? 128 : 64;
    constexpr int LDA = K + 8;              // halfs; %8==0
    constexpr int LDB = 136;                // 128+8 halfs
    constexpr int STAGE_BYTES = (64 * LDA + 64 * LDB) * 2;
    constexpr int SMEM_BYTES  = (STAGE_BYTES > 64 * 128 * 4) ? STAGE_BYTES
                                                             : 64 * 128 * 4;
    __shared__ alignas(16) char sraw[SMEM_BYTES];
    __half* sA = (__half*)sraw;                       // 64 x LDA
    __half* sB = (__half*)(sraw + 64 * LDA * 2);      // 64 x LDB (per chunk)
    float*  sC = (float*)sraw;                        // 64 x 128 (epilogue alias)

    const __half* A  = (LAYER == 1) ? g_xh  : g_yh;
    const __half* Wh = (LAYER == 1) ? g_W1h : g_W2h;

    int tid   = threadIdx.x;
    int wid   = tid >> 5;
    int rw    = (wid & 3) * 16;             // warp row in tile
    int cw    = (wid >> 2) * 64;            // warp col in tile
    int rbase = blockIdx.x * 64;
    int colb  = blockIdx.y * 128;

    // stage A tile: 64 rows x K halfs (int4 = 8 halfs)
    constexpr int AI4 = K / 8;              // int4 per row
    const int4* gA = (const int4*)(A + (size_t)rbase * K);
    for (int idx = tid; idx < 64 * AI4; idx += 256) {
        int r = idx / AI4, c = idx - r * AI4;
        ((int4*)(sA + r * LDA))[c] = gA[r * AI4 + c];
    }

    wmma::fragment<wmma::accumulator, 16, 16, 16, float> c[4];
#pragma unroll
    for (int i = 0; i < 4; i++) wmma::fill_fragment(c[i], 0.f);

#pragma unroll
    for (int kc = 0; kc < K; kc += 64) {
        // stage W chunk: rows kc..kc+63, cols colb..colb+127 (16 int4/row)
        for (int idx = tid; idx < 64 * 16; idx += 256) {
            int r = idx >> 4, cc = idx & 15;
            ((int4*)(sB + r * LDB))[cc] =
                *(const int4*)(Wh + (size_t)(kc + r) * 256 + colb + cc * 8);
        }
        __syncthreads();   // covers sA staging on first pass too

#pragma unroll
        for (int k = 0; k < 64; k += 16) {
            wmma::fragment<wmma::matrix_a, 16, 16, 16, __half, wmma::row_major> a;
            wmma::load_matrix_sync(a, sA + rw * LDA + kc + k, LDA);
#pragma unroll
            for (int i = 0; i < 4; i++) {
                wmma::fragment<wmma::matrix_b, 16, 16, 16, __half, wmma::row_major> b;
                wmma::load_matrix_sync(b, sB + k * LDB + cw + i * 16, LDB);
                wmma::mma_sync(c[i], a, b, c[i]);
            }
        }
        __syncthreads();   // before next chunk overwrites sB (and before sC alias)
    }

    // epilogue: fp32 tile in shared (aliases staging), convert to fp16 out
#pragma unroll
    for (int i = 0; i < 4; i++)
        wmma::store_matrix_sync(sC + rw * 128 + cw + i * 16, c[i], 128,
                                wmma::mem_row_major);
    __syncthreads();

    for (int idx = tid; idx < 64 * 64; idx += 256) {
        int r = idx >> 6, cp = idx & 63;
        float2 f = *(float2*)(sC + r * 128 + cp * 2);
        *(__half2*)(g_hh + (size_t)(rbase + r) * 256 + colb + cp * 2) =
            __floats2half2_rn(f.x, f.y);
    }
}

// ---------------------------------------------------------------------------
// Attention coefficients: g_a[n][j] = X[n,:] . Wa[j,:]  (fp32, exact).
// ---------------------------------------------------------------------------
template <int LAYER>
__global__ void __launch_bounds__(256) attn_lin(const float* __restrict__ Xin, int Nn) {
    constexpr int K  = (LAYER == 1) ? 128 : 64;
    constexpr int NI = K / 32;
    const float* Wa = (LAYER == 1) ? g_Wa1 : g_Wa2;
    const float* X  = (LAYER == 1) ? Xin   : g_y;

    __shared__ float sWa[8 * K];
    for (int i = threadIdx.x; i < 8 * K; i += 256) sWa[i] = Wa[i];
    __syncthreads();

    int warp = (blockIdx.x * blockDim.x + threadIdx.x) >> 5;
    int lane = threadIdx.x & 31;
    if (warp >= Nn) return;
    int n = warp;

    float xv[NI];
#pragma unroll
    for (int i = 0; i < NI; i++) xv[i] = X[(size_t)n * K + i * 32 + lane];

    float d[8];
#pragma unroll
    for (int j = 0; j < 8; j++) {
        float s = 0.f;
#pragma unroll
        for (int i = 0; i < NI; i++)
            s = fmaf(xv[i], sWa[j * K + i * 32 + lane], s);
#pragma unroll
        for (int off = 16; off; off >>= 1)
            s += __shfl_xor_sync(0xffffffffu, s, off);
        d[j] = s;
    }
    if (lane == 0) {
        float4* out = (float4*)(g_a + (size_t)n * 8);
        out[0] = make_float4(d[0], d[1], d[2], d[3]);
        out[1] = make_float4(d[4], d[5], d[6], d[7]);
    }
}

// ---------------------------------------------------------------------------
// GAT aggregation: static warp-per-node, warp-batched edge ids (32 per
// coalesced LDG, broadcast via shfl).  Lane l covers cols [8l, 8l+8).
// ---------------------------------------------------------------------------
template <bool RELU, bool TO_Y>
__global__ void __launch_bounds__(256) gat_aggregate(const float* __restrict__ bias,
                                                     float* __restrict__ outp, int Nn) {
    int warp = (blockIdx.x * blockDim.x + threadIdx.x) >> 5;
    int lane = threadIdx.x & 31;
    if (warp >= Nn) return;
    int n    = warp;
    int beg  = g_off[n];
    int cnt  = g_counts[n];
    int h    = lane >> 3;
    int sub  = lane & 7;

    float adv = g_a[(size_t)n * 8 + 4 + h];

    float acc[8];
#pragma unroll
    for (int i = 0; i < 8; i++) acc[i] = 0.f;
    float sw = 0.f;

    for (int jb = 0; jb < cnt; jb += 32) {
        int m  = cnt - jb; if (m > 32) m = 32;
        int sv = (jb + lane < cnt) ? g_csrc[beg + jb + lane] : 0;

        int k = 0;
        for (; k + 2 <= m; k += 2) {
            int s0 = __shfl_sync(0xffffffffu, sv, k);
            int s1 = __shfl_sync(0xffffffffu, sv, k + 1);
            float e0 = __ldg(g_a + (size_t)s0 * 8 + h) + adv;
            float e1 = __ldg(g_a + (size_t)s1 * 8 + h) + adv;
            float4 r0 = *((const float4*)(g_hh + (size_t)s0 * 256) + lane);
            float4 r1 = *((const float4*)(g_hh + (size_t)s1 * 256) + lane);
            e0 = (e0 > 0.f) ? e0 : 0.2f * e0;
            e1 = (e1 > 0.f) ? e1 : 0.2f * e1;
            float w0 = __expf(e0), w1 = __expf(e1);
            sw += w0 + w1;
            {
                const __half2* hp = (const __half2*)&r0;
                float2 f0 = __half22float2(hp[0]), f1 = __half22float2(hp[1]);
                float2 f2 = __half22float2(hp[2]), f3 = __half22float2(hp[3]);
                acc[0] = fmaf(w0, f0.x, acc[0]); acc[1] = fmaf(w0, f0.y, acc[1]);
                acc[2] = fmaf(w0, f1.x, acc[2]); acc[3] = fmaf(w0, f1.y, acc[3]);
                acc[4] = fmaf(w0, f2.x, acc[4]); acc[5] = fmaf(w0, f2.y, acc[5]);
                acc[6] = fmaf(w0, f3.x, acc[6]); acc[7] = fmaf(w0, f3.y, acc[7]);
            }
            {
                const __half2* hp = (const __half2*)&r1;
                float2 f0 = __half22float2(hp[0]), f1 = __half22float2(hp[1]);
                float2 f2 = __half22float2(hp[2]), f3 = __half22float2(hp[3]);
                acc[0] = fmaf(w1, f0.x, acc[0]); acc[1] = fmaf(w1, f0.y, acc[1]);
                acc[2] = fmaf(w1, f1.x, acc[2]); acc[3] = fmaf(w1, f1.y, acc[3]);
                acc[4] = fmaf(w1, f2.x, acc[4]); acc[5] = fmaf(w1, f2.y, acc[5]);
                acc[6] = fmaf(w1, f3.x, acc[6]); acc[7] = fmaf(w1, f3.y, acc[7]);
            }
        }
        if (k < m) {
            int s = __shfl_sync(0xffffffffu, sv, k);
            float e = __ldg(g_a + (size_t)s * 8 + h) + adv;
            e = (e > 0.f) ? e : 0.2f * e;
            float w = __expf(e);
            sw += w;
            float4 raw = *((const float4*)(g_hh + (size_t)s * 256) + lane);
            const __half2* hp = (const __half2*)&raw;
            float2 f0 = __half22float2(hp[0]), f1 = __half22float2(hp[1]);
            float2 f2 = __half22float2(hp[2]), f3 = __half22float2(hp[3]);
            acc[0] = fmaf(w, f0.x, acc[0]); acc[1] = fmaf(w, f0.y, acc[1]);
            acc[2] = fmaf(w, f1.x, acc[2]); acc[3] = fmaf(w, f1.y, acc[3]);
            acc[4] = fmaf(w, f2.x, acc[4]); acc[5] = fmaf(w, f2.y, acc[5]);
            acc[6] = fmaf(w, f3.x, acc[6]); acc[7] = fmaf(w, f3.y, acc[7]);
        }
    }

    float r = 1.f / (sw + 1e-16f);
#pragma unroll
    for (int i = 0; i < 8; i++) {
        acc[i] *= r;
        acc[i] += __shfl_xor_sync(0xffffffffu, acc[i], 8);
        acc[i] += __shfl_xor_sync(0xffffffffu, acc[i], 16);
    }

    if (h == 0) {   // lanes 0..7: 4-head sums for cols [8*sub, 8*sub+8)
        int c0 = sub * 8;
        float4 b0 = *(const float4*)(bias + c0);
        float4 b1 = *(const float4*)(bias + c0 + 4);
        float4 o0, o1;
        o0.x = 0.25f * acc[0] + b0.x;  o0.y = 0.25f * acc[1] + b0.y;
        o0.z = 0.25f * acc[2] + b0.z;  o0.w = 0.25f * acc[3] + b0.w;
        o1.x = 0.25f * acc[4] + b1.x;  o1.y = 0.25f * acc[5] + b1.y;
        o1.z = 0.25f * acc[6] + b1.z;  o1.w = 0.25f * acc[7] + b1.w;
        if (RELU) {
            o0.x = fmaxf(o0.x, 0.f); o0.y = fmaxf(o0.y, 0.f);
            o0.z = fmaxf(o0.z, 0.f); o0.w = fmaxf(o0.w, 0.f);
            o1.x = fmaxf(o1.x, 0.f); o1.y = fmaxf(o1.y, 0.f);
            o1.z = fmaxf(o1.z, 0.f); o1.w = fmaxf(o1.w, 0.f);
        }
        float* out = TO_Y ? g_y : outp;
        *(float4*)(out + (size_t)n * 64 + c0)     = o0;
        *(float4*)(out + (size_t)n * 64 + c0 + 4) = o1;
        if (TO_Y) {  // fp16 shadow for GEMM2's A operand
            __half2* yh = (__half2*)(g_yh + (size_t)n * 64 + c0);
            yh[0] = __floats2half2_rn(o0.x, o0.y);
            yh[1] = __floats2half2_rn(o0.z, o0.w);
            yh[2] = __floats2half2_rn(o1.x, o1.y);
            yh[3] = __floats2half2_rn(o1.z, o1.w);
        }
    }
}

// ---------------------------------------------------------------------------
extern "C" void kernel_launch(void* const* d_in, const int* in_sizes, int n_in,
                              void* d_out, int out_size) {
    const float* x   = (const float*)d_in[0];
    const void*  ei  = d_in[1];
    const float* W1  = (const float*)d_in[2];
    const float* as1 = (const float*)d_in[3];
    const float* ad1 = (const float*)d_in[4];
    const float* b1  = (const float*)d_in[5];
    const float* W2  = (const float*)d_in[6];
    const float* as2 = (const float*)d_in[7];
    const float* ad2 = (const float*)d_in[8];
    const float* b2  = (const float*)d_in[9];

    int N  = in_sizes[0] / 128;
    int E  = in_sizes[1] / 2;
    int EA = E + N;

    int nodeWarpBlocks = (N + 7) / 8;   // 256 thr = 8 warps/block
    dim3 ggrid(NPAD / 64, 2);

    // launches 0-2: preamble + CSR counts/offsets
    prep_kernel<<<256, 256>>>(x, W1, W2, as1, ad1, as2, ad2, ei, N, E);
    count_kernel<<<(EA + 255) / 256, 256>>>(ei, E, N);
    offsets_kernel<<<(N + 255) / 256, 256>>>(N);
    // launch 3 (= ncu capture slot): layer-1 GEMM
    wmma_gemm<1><<<ggrid, 256>>>();
    // launch 4: scatter (independent of gemm; must precede aggregate)
    scatter_kernel<<<(EA + 255) / 256, 256>>>(ei, E, N);

    // ---- layer 1 ----
    attn_lin<1><<<nodeWarpBlocks, 256>>>(x, N);
    gat_aggregate<true, true><<<nodeWarpBlocks, 256>>>(b1, nullptr, N);

    // ---- layer 2 ----
    wmma_gemm<2><<<ggrid, 256>>>();
    attn_lin<2><<<nodeWarpBlocks, 256>>>(nullptr, N);
    gat_aggregate<false, false><<<nodeWarpBlocks, 256>>>(b2, (float*)d_out, N);
}